// round 1
// baseline (speedup 1.0000x reference)
#include <cuda_runtime.h>
#include <cuda_bf16.h>

// Problem constants
#define NB     32      // batch
#define NZ     100
#define STATE  20
#define HIDN   128
#define HH     32
#define WW     32
#define STEPS  64
#define THRESH 0.1f

#define PIXELS_PER_IMG (HH*WW)                 // 1024
#define STATE_SZ (NB*STATE*PIXELS_PER_IMG)     // 655360 floats

// ---------------- device scratch (no allocations allowed) ----------------
__device__ __align__(16) float g_S0[STATE_SZ];
__device__ __align__(16) float g_S1[STATE_SZ];
__device__ __align__(16) float g_T [STATE_SZ];
__device__ unsigned char      g_P [NB*PIXELS_PER_IMG];
// packed weights: w_perc -> [cr=0..59][hid=0..127][4 slots (3 used)]
__device__ __align__(16) float g_wp_pad [60*128*4];
// w_up1 -> [kg=0..31][hid][4]
__device__ __align__(16) float g_wu1_pad[32*128*4];

// ---------------- weight repack ----------------
__global__ void k_pack(const float* __restrict__ wp, const float* __restrict__ wu1)
{
    int i = blockIdx.x*256 + threadIdx.x;
    if (i < 128*180) {
        int h = i / 180, k = i % 180;            // k = c*9 + r*3 + kx
        g_wp_pad[(k/3)*512 + h*4 + (k%3)] = wp[i];
    }
    if (i < 128*128) {
        int h = i / 128, k = i % 128;
        g_wu1_pad[(k>>2)*512 + h*4 + (k&3)] = wu1[i];
    }
}

// ---------------- zero initial state ----------------
__global__ void k_zero()
{
    int i = blockIdx.x*256 + threadIdx.x;
    if (i < STATE_SZ) g_S0[i] = 0.f;
}

// ---------------- init MLP: z -> center pixel ----------------
__global__ void k_init(const float* __restrict__ z,
                       const float* __restrict__ w1, const float* __restrict__ b1,
                       const float* __restrict__ w2, const float* __restrict__ b2)
{
    int n = blockIdx.x;
    int t = threadIdx.x;  // 128 threads
    __shared__ float zz[NZ];
    __shared__ float h[50];
    if (t < NZ) zz[t] = z[n*NZ + t];
    __syncthreads();
    if (t < 50) {
        float a = b1[t];
        #pragma unroll 4
        for (int j = 0; j < NZ; j++) a += w1[t*NZ + j] * zz[j];
        h[t] = fmaxf(a, 0.f);
    }
    __syncthreads();
    const int ctr = 16*WW + 16;
    if (t < STATE-1) {
        float a = b2[t];
        #pragma unroll 5
        for (int j = 0; j < 50; j++) a += w2[t*50 + j] * h[j];
        g_S0[n*STATE*PIXELS_PER_IMG + (1+t)*PIXELS_PER_IMG + ctr] = a;
    }
    if (t == STATE-1) {
        g_S0[n*STATE*PIXELS_PER_IMG + 0*PIXELS_PER_IMG + ctr] = 0.5f;
    }
}

// ---------------- step kernel 1: perceive + MLP, write s_tmp + pre-mask ----------------
// grid: (4, 32, 32) = (strip, row, image); block: 128 threads (1 thread = 1 HID channel)
__global__ void __launch_bounds__(128)
k_step1(int pin,
        const float* __restrict__ bp,
        const float* __restrict__ bu1,
        const float* __restrict__ wu2, const float* __restrict__ bu2)
{
    const int x0 = blockIdx.x * 8;
    const int y  = blockIdx.y;
    const int n  = blockIdx.z;
    const int t  = threadIdx.x;

    const float* __restrict__ S = pin ? g_S1 : g_S0;
    const float* __restrict__ Sn = S + n*STATE*PIXELS_PER_IMG;
    float* __restrict__ Tn = g_T + n*STATE*PIXELS_PER_IMG;

    // ---- dead-strip test: ch0 over rows y-2..y+2, cols x0-2..x0+9 ----
    int hot = 0;
    if (t < 60) {
        int r  = t / 12, c = t % 12;
        int yy = y - 2 + r, xx = x0 - 2 + c;
        if ((unsigned)yy < (unsigned)HH && (unsigned)xx < (unsigned)WW)
            hot = Sn[yy*WW + xx] > THRESH;
    }
    if (!__syncthreads_or(hot)) {
        // whole strip (and all its neighbors) is pre-dead: outputs are 0
        #pragma unroll
        for (int i = t; i < 160; i += 128) {
            int c = i >> 3, p = i & 7;
            Tn[c*PIXELS_PER_IMG + y*WW + x0 + p] = 0.f;
        }
        if (t < 8) g_P[n*PIXELS_PER_IMG + y*WW + x0 + t] = 0;
        return;
    }

    __shared__ float patch[STATE][3][12];   // rows y-1..y+1, cols x0-1..x0+8 (+2 pad)
    __shared__ float s_perc[HIDN][8];
    __shared__ float s_h2 [HIDN][8];

    for (int i = t; i < STATE*3*12; i += 128) {
        int c = i / 36, rem = i - c*36, r = rem / 12, col = rem - r*12;
        int yy = y - 1 + r, xx = x0 - 1 + col;
        float v = 0.f;
        if (col < 10 && (unsigned)yy < (unsigned)HH && (unsigned)xx < (unsigned)WW)
            v = Sn[c*PIXELS_PER_IMG + yy*WW + xx];
        patch[c][r][col] = v;
    }
    __syncthreads();

    // pre living mask for the 8 strip pixels
    if (t < 8) {
        float m = 0.f;
        #pragma unroll
        for (int r = 0; r < 3; r++)
            #pragma unroll
            for (int cc = 0; cc < 3; cc++)
                m = fmaxf(m, patch[0][r][t + cc]);
        g_P[n*PIXELS_PER_IMG + y*WW + x0 + t] = (m > THRESH) ? 1 : 0;
    }

    // ---- perceive: 3x3 conv, 20 -> 128, thread t computes channel t for 8 pixels ----
    float acc[8];
    {
        float b = bp[t];
        #pragma unroll
        for (int p = 0; p < 8; p++) acc[p] = b;
    }
    #pragma unroll 2
    for (int c = 0; c < STATE; c++) {
        #pragma unroll
        for (int r = 0; r < 3; r++) {
            const float4 a = *(const float4*)&patch[c][r][0];
            const float4 b = *(const float4*)&patch[c][r][4];
            const float4 d = *(const float4*)&patch[c][r][8];
            float rv[12] = {a.x,a.y,a.z,a.w, b.x,b.y,b.z,b.w, d.x,d.y,d.z,d.w};
            const float4 w4 = *(const float4*)&g_wp_pad[(c*3 + r)*512 + t*4];
            float wk[3] = {w4.x, w4.y, w4.z};
            #pragma unroll
            for (int kx = 0; kx < 3; kx++)
                #pragma unroll
                for (int p = 0; p < 8; p++)
                    acc[p] = fmaf(wk[kx], rv[p + kx], acc[p]);
        }
    }
    #pragma unroll
    for (int p = 0; p < 8; p++) s_perc[t][p] = acc[p];
    __syncthreads();

    // ---- up1: 1x1 conv 128 -> 128 + ReLU ----
    float acc2[8];
    {
        float b = bu1[t];
        #pragma unroll
        for (int p = 0; p < 8; p++) acc2[p] = b;
    }
    #pragma unroll 4
    for (int kg = 0; kg < 32; kg++) {
        const float4 w4 = *(const float4*)&g_wu1_pad[kg*512 + t*4];
        float wk[4] = {w4.x, w4.y, w4.z, w4.w};
        #pragma unroll
        for (int j = 0; j < 4; j++) {
            int k = kg*4 + j;
            const float4 va = *(const float4*)&s_perc[k][0];
            const float4 vb = *(const float4*)&s_perc[k][4];
            acc2[0] = fmaf(wk[j], va.x, acc2[0]);
            acc2[1] = fmaf(wk[j], va.y, acc2[1]);
            acc2[2] = fmaf(wk[j], va.z, acc2[2]);
            acc2[3] = fmaf(wk[j], va.w, acc2[3]);
            acc2[4] = fmaf(wk[j], vb.x, acc2[4]);
            acc2[5] = fmaf(wk[j], vb.y, acc2[5]);
            acc2[6] = fmaf(wk[j], vb.z, acc2[6]);
            acc2[7] = fmaf(wk[j], vb.w, acc2[7]);
        }
    }
    #pragma unroll
    for (int p = 0; p < 8; p++) s_h2[t][p] = fmaxf(acc2[p], 0.f);
    __syncthreads();

    // ---- up2: 1x1 conv 128 -> 20, then s_tmp = s_old + upd ----
    {
        int c = t >> 3, p = t & 7;
        float a = bu2[c];
        #pragma unroll 8
        for (int k4 = 0; k4 < 32; k4++) {
            const float4 w4 = *(const float4*)&wu2[c*128 + k4*4];
            a = fmaf(w4.x, s_h2[k4*4+0][p], a);
            a = fmaf(w4.y, s_h2[k4*4+1][p], a);
            a = fmaf(w4.z, s_h2[k4*4+2][p], a);
            a = fmaf(w4.w, s_h2[k4*4+3][p], a);
        }
        Tn[c*PIXELS_PER_IMG + y*WW + x0 + p] = patch[c][1][p+1] + a;
    }
    if (t < 32) {
        int i = t + 128;
        int c = i >> 3, p = i & 7;
        float a = bu2[c];
        #pragma unroll 8
        for (int k4 = 0; k4 < 32; k4++) {
            const float4 w4 = *(const float4*)&wu2[c*128 + k4*4];
            a = fmaf(w4.x, s_h2[k4*4+0][p], a);
            a = fmaf(w4.y, s_h2[k4*4+1][p], a);
            a = fmaf(w4.z, s_h2[k4*4+2][p], a);
            a = fmaf(w4.w, s_h2[k4*4+3][p], a);
        }
        Tn[c*PIXELS_PER_IMG + y*WW + x0 + p] = patch[c][1][p+1] + a;
    }
}

// ---------------- step kernel 2: post mask + apply ----------------
__global__ void __launch_bounds__(256)
k_step2(int pout)
{
    int g = blockIdx.x*256 + threadIdx.x;     // 0..32767
    int n = g >> 10, rem = g & 1023;
    int y = rem >> 5, x = rem & 31;
    float* __restrict__ So = (pout ? g_S1 : g_S0) + n*STATE*PIXELS_PER_IMG;
    const float* __restrict__ Tn = g_T + n*STATE*PIXELS_PER_IMG;

    bool alive = false;
    if (g_P[g]) {
        float m = 0.f;
        #pragma unroll
        for (int dy = -1; dy <= 1; dy++) {
            int yy = y + dy;
            if ((unsigned)yy >= (unsigned)HH) continue;
            #pragma unroll
            for (int dx = -1; dx <= 1; dx++) {
                int xx = x + dx;
                if ((unsigned)xx >= (unsigned)WW) continue;
                m = fmaxf(m, Tn[yy*WW + xx]);
            }
        }
        alive = m > THRESH;
    }
    if (alive) {
        #pragma unroll
        for (int c = 0; c < STATE; c++) So[c*PIXELS_PER_IMG + rem] = Tn[c*PIXELS_PER_IMG + rem];
    } else {
        #pragma unroll
        for (int c = 0; c < STATE; c++) So[c*PIXELS_PER_IMG + rem] = 0.f;
    }
}

// ---------------- extract output: ch0 of final state ----------------
__global__ void k_extract(float* __restrict__ out)
{
    int g = blockIdx.x*256 + threadIdx.x;     // 0..32767
    int n = g >> 10, rem = g & 1023;
    out[g] = g_S0[n*STATE*PIXELS_PER_IMG + rem];
}

// ---------------- launch ----------------
extern "C" void kernel_launch(void* const* d_in, const int* in_sizes, int n_in,
                              void* d_out, int out_size)
{
    const float* z   = (const float*)d_in[0];
    const float* w1  = (const float*)d_in[1];
    const float* b1  = (const float*)d_in[2];
    const float* w2  = (const float*)d_in[3];
    const float* b2  = (const float*)d_in[4];
    const float* wp  = (const float*)d_in[5];
    const float* bp  = (const float*)d_in[6];
    const float* wu1 = (const float*)d_in[7];
    const float* bu1 = (const float*)d_in[8];
    const float* wu2 = (const float*)d_in[9];
    const float* bu2 = (const float*)d_in[10];
    float* out = (float*)d_out;

    k_pack<<<(128*180 + 255)/256, 256>>>(wp, wu1);
    k_zero<<<(STATE_SZ + 255)/256, 256>>>();
    k_init<<<NB, 128>>>(z, w1, b1, w2, b2);

    for (int t = 0; t < STEPS; t++) {
        int pin  = t & 1;
        int pout = pin ^ 1;
        k_step1<<<dim3(4, 32, 32), 128>>>(pin, bp, bu1, wu2, bu2);
        k_step2<<<(NB*PIXELS_PER_IMG)/256, 256>>>(pout);
    }
    k_extract<<<(NB*PIXELS_PER_IMG)/256, 256>>>(out);
}